// round 14
// baseline (speedup 1.0000x reference)
#include <cuda_runtime.h>
#include <math.h>

// Problem constants (match reference)
#define NNODES 100000
#define NEDGES 1600000
#define FEATP  144          // FEAT=131 padded to multiple of 16
#define HID    128

// ---------------- scratch (device globals; no allocation) ----------------
__device__ float d_node[(size_t)NNODES * FEATP];   // gelu'd concat features
__device__ float d_g  [(size_t)NNODES * HID];      // per-layer GEMM output h = x@W
__device__ float d_h  [(size_t)NNODES * HID];      // layer0 aggregated (relu) output
__device__ float d_w0p[FEATP * HID];               // padded W0
__device__ float d_as [NNODES];
__device__ float d_ad [NNODES];
__device__ float d_ang[NNODES * 2];
__device__ float d_dis[NNODES * 2];
__device__ int   d_counts[NNODES];
__device__ int   d_rowptr[NNODES + 1];
__device__ int   d_woff  [NNODES];
__device__ int   d_csrsrc[NEDGES];

// ---------------- helpers ----------------
__device__ __forceinline__ unsigned long long pk2(float lo, float hi) {
    unsigned long long r;
    asm("mov.b64 %0, {%1,%2};" : "=l"(r) : "f"(lo), "f"(hi));
    return r;
}
__device__ __forceinline__ float2 upk2(unsigned long long v) {
    float2 f;
    asm("mov.b64 {%0,%1}, %2;" : "=f"(f.x), "=f"(f.y) : "l"(v));
    return f;
}
__device__ __forceinline__ void ffma2(unsigned long long& d, unsigned long long a, unsigned long long b) {
    asm("fma.rn.f32x2 %0, %1, %2, %0;" : "+l"(d) : "l"(a), "l"(b));
}
__device__ __forceinline__ float gelu_exact(float x) {
    return 0.5f * x * (1.0f + erff(x * 0.70710678118654752440f));
}
__device__ __forceinline__ float lrelu(float x) { return x >= 0.f ? x : 0.2f * x; }

// ---------------- zero scratch ----------------
__global__ void zero_kernel(int nf4, int n) {
    int stride = gridDim.x * blockDim.x;
    int i = blockIdx.x * blockDim.x + threadIdx.x;
    float4 z = make_float4(0.f, 0.f, 0.f, 0.f);
    for (int j = i; j < nf4; j += stride) reinterpret_cast<float4*>(d_node)[j] = z;
    for (int j = i; j < n;   j += stride) d_counts[j] = 0;
}

// ---------------- pad W0 (131x128 -> 144x128, zero rows) ----------------
__global__ void w0pad_kernel(const float* __restrict__ W0) {
    int i = blockIdx.x * blockDim.x + threadIdx.x;
    if (i < FEATP * HID) {
        int r = i / HID;
        d_w0p[i] = (r < 131) ? W0[i] : 0.f;
    }
}

// ---------------- generic fp32 GEMM with f32x2 ----------------
// C[scatter(m), cb+n] = act( sum_k A[m,k]*W[k, cb+n] + bias[cb+n] )
// tile: BM=128, BN=64 (per blockIdx.y), BK=16; 256 threads; thread = 4 rows x 8 cols
__global__ __launch_bounds__(256)
void gemm_kernel(const float* __restrict__ A, int lda, int K,
                 const float* __restrict__ W, int ldw,
                 const float* __restrict__ bias,
                 float* __restrict__ C, int ldc,
                 const int* __restrict__ scatter,
                 int act, int nrows)
{
    __shared__ float As[16][129];
    __shared__ float Bs[16][64];

    int tid   = threadIdx.x;
    int mbase = blockIdx.x * 128;
    int cb    = blockIdx.y * 64;

    int tm = (tid / 8) * 4;       // 0..124
    int tn = (tid % 8) * 8;       // 0..56

    unsigned long long acc[4][4];
#pragma unroll
    for (int i = 0; i < 4; i++)
#pragma unroll
        for (int j = 0; j < 4; j++) acc[i][j] = 0ull;

    int arow = tid / 4;           // 0..63
    int acol = (tid % 4) * 4;     // 0..12
    int wrow = tid / 16;          // 0..15
    int wcol = (tid % 16) * 4;    // 0..60

    for (int k0 = 0; k0 < K; k0 += 16) {
#pragma unroll
        for (int p = 0; p < 2; p++) {
            int r = mbase + arow + p * 64;
            float4 v = make_float4(0.f, 0.f, 0.f, 0.f);
            if (r < nrows) v = *reinterpret_cast<const float4*>(A + (size_t)r * lda + k0 + acol);
            As[acol + 0][arow + p * 64] = v.x;
            As[acol + 1][arow + p * 64] = v.y;
            As[acol + 2][arow + p * 64] = v.z;
            As[acol + 3][arow + p * 64] = v.w;
        }
        {
            float4 v = *reinterpret_cast<const float4*>(W + (size_t)(k0 + wrow) * ldw + cb + wcol);
            *reinterpret_cast<float4*>(&Bs[wrow][wcol]) = v;
        }
        __syncthreads();

#pragma unroll
        for (int k = 0; k < 16; k++) {
            unsigned long long a2[4];
#pragma unroll
            for (int i = 0; i < 4; i++) { float a = As[k][tm + i]; a2[i] = pk2(a, a); }
            float4 bA = *reinterpret_cast<const float4*>(&Bs[k][tn]);
            float4 bB = *reinterpret_cast<const float4*>(&Bs[k][tn + 4]);
            unsigned long long b2[4];
            b2[0] = pk2(bA.x, bA.y); b2[1] = pk2(bA.z, bA.w);
            b2[2] = pk2(bB.x, bB.y); b2[3] = pk2(bB.z, bB.w);
#pragma unroll
            for (int i = 0; i < 4; i++)
#pragma unroll
                for (int j = 0; j < 4; j++) ffma2(acc[i][j], a2[i], b2[j]);
        }
        __syncthreads();
    }

#pragma unroll
    for (int i = 0; i < 4; i++) {
        int r = mbase + tm + i;
        if (r >= nrows) break;
        int tr = scatter ? scatter[r] : r;
        float o[8];
#pragma unroll
        for (int j = 0; j < 4; j++) { float2 f = upk2(acc[i][j]); o[2 * j] = f.x; o[2 * j + 1] = f.y; }
#pragma unroll
        for (int j = 0; j < 8; j++) {
            float v = o[j] + (bias ? bias[cb + tn + j] : 0.f);
            if (act == 1) v = gelu_exact(v);
            o[j] = v;
        }
        float* dst = C + (size_t)tr * ldc + cb + tn;
        *reinterpret_cast<float4*>(dst)     = make_float4(o[0], o[1], o[2], o[3]);
        *reinterpret_cast<float4*>(dst + 4) = make_float4(o[4], o[5], o[6], o[7]);
    }
}

// ---------------- ars columns (128..130) with gelu, scattered ----------------
__global__ void ars_kernel(const float* __restrict__ ars, const int* __restrict__ ci, int n) {
    int r = blockIdx.x * blockDim.x + threadIdx.x;
    if (r < n) {
        int t = ci[r];
        float* dst = d_node + (size_t)t * FEATP + 128;
        dst[0] = gelu_exact(ars[r * 3 + 0]);
        dst[1] = gelu_exact(ars[r * 3 + 1]);
        dst[2] = gelu_exact(ars[r * 3 + 2]);
    }
}

// ---------------- CSR build ----------------
__global__ void count_kernel(const int* __restrict__ edges, int E) {
    int e = blockIdx.x * blockDim.x + threadIdx.x;
    if (e < E) atomicAdd(&d_counts[edges[2 * e + 1]], 1);
}

__global__ void scan_kernel(int n) {
    __shared__ int sm[1024];
    int tid = threadIdx.x;
    int per = (n + 1023) >> 10;
    int start = tid * per;
    int s = 0;
    for (int i = 0; i < per; i++) { int idx = start + i; if (idx < n) s += d_counts[idx]; }
    sm[tid] = s;
    __syncthreads();
    for (int off = 1; off < 1024; off <<= 1) {
        int v = (tid >= off) ? sm[tid - off] : 0;
        __syncthreads();
        sm[tid] += v;
        __syncthreads();
    }
    int run = sm[tid] - s;   // exclusive prefix
    for (int i = 0; i < per; i++) {
        int idx = start + i;
        if (idx < n) { d_rowptr[idx] = run; d_woff[idx] = run; run += d_counts[idx]; }
    }
    if (tid == 1023) d_rowptr[n] = sm[1023];
}

__global__ void scatter_kernel(const int* __restrict__ edges, int E) {
    int e = blockIdx.x * blockDim.x + threadIdx.x;
    if (e < E) {
        int s = edges[2 * e];
        int d = edges[2 * e + 1];
        int p = atomicAdd(&d_woff[d], 1);
        d_csrsrc[p] = s;
    }
}

// ---------------- attention scores a_s, a_d (warp per node) ----------------
__global__ void attn_kernel(const float* __restrict__ g,
                            const float* __restrict__ av_s,
                            const float* __restrict__ av_d, int n) {
    int lane = threadIdx.x & 31;
    int node = (blockIdx.x * blockDim.x + threadIdx.x) >> 5;
    if (node >= n) return;
    float4 h = *reinterpret_cast<const float4*>(g + (size_t)node * 128 + lane * 4);
    float4 a = *reinterpret_cast<const float4*>(av_s + lane * 4);
    float4 b = *reinterpret_cast<const float4*>(av_d + lane * 4);
    float ps = h.x * a.x + h.y * a.y + h.z * a.z + h.w * a.w;
    float pd = h.x * b.x + h.y * b.y + h.z * b.z + h.w * b.w;
#pragma unroll
    for (int o = 16; o; o >>= 1) {
        ps += __shfl_xor_sync(0xffffffffu, ps, o);
        pd += __shfl_xor_sync(0xffffffffu, pd, o);
    }
    if (lane == 0) { d_as[node] = ps; d_ad[node] = pd; }
}

// ---------------- GAT aggregation (warp per destination node) ----------------
// act: 1=relu, 2=gelu
__global__ void agg_kernel(const float* __restrict__ g,
                           const float* __restrict__ bias,
                           float* __restrict__ out, int act, int n) {
    int lane = threadIdx.x & 31;
    int node = (blockIdx.x * blockDim.x + threadIdx.x) >> 5;
    if (node >= n) return;

    float adv = d_ad[node];
    float e_self = lrelu(d_as[node] + adv);
    int r0 = d_rowptr[node], r1 = d_rowptr[node + 1];

    // pass 1: segment max (includes self loop)
    float m = e_self;
    for (int j = r0 + lane; j < r1; j += 32)
        m = fmaxf(m, lrelu(d_as[d_csrsrc[j]] + adv));
#pragma unroll
    for (int o = 16; o; o >>= 1) m = fmaxf(m, __shfl_xor_sync(0xffffffffu, m, o));

    // pass 2: weighted accumulate (all lanes walk all edges; lane owns 4 cols)
    float wself = __expf(e_self - m);
    float denom = wself;
    float4 hv = *reinterpret_cast<const float4*>(g + (size_t)node * 128 + lane * 4);
    float4 acc;
    acc.x = wself * hv.x; acc.y = wself * hv.y; acc.z = wself * hv.z; acc.w = wself * hv.w;
    for (int j = r0; j < r1; ++j) {
        int s = d_csrsrc[j];
        float w = __expf(lrelu(d_as[s] + adv) - m);
        denom += w;
        float4 hs = *reinterpret_cast<const float4*>(g + (size_t)s * 128 + lane * 4);
        acc.x += w * hs.x; acc.y += w * hs.y; acc.z += w * hs.z; acc.w += w * hs.w;
    }
    float inv = 1.f / (denom + 1e-16f);
    float4 bv = *reinterpret_cast<const float4*>(bias + lane * 4);
    float4 o;
    o.x = acc.x * inv + bv.x; o.y = acc.y * inv + bv.y;
    o.z = acc.z * inv + bv.z; o.w = acc.w * inv + bv.w;
    if (act == 1) {
        o.x = fmaxf(o.x, 0.f); o.y = fmaxf(o.y, 0.f); o.z = fmaxf(o.z, 0.f); o.w = fmaxf(o.w, 0.f);
    } else {
        o.x = gelu_exact(o.x); o.y = gelu_exact(o.y); o.z = gelu_exact(o.z); o.w = gelu_exact(o.w);
    }
    *reinterpret_cast<float4*>(out + (size_t)node * 128 + lane * 4) = o;
}

// ---------------- heads: angles/dists (warp per node) ----------------
__global__ void head_kernel(const float* __restrict__ out,
                            const float* __restrict__ Wa, const float* __restrict__ ba,
                            const float* __restrict__ Wd, const float* __restrict__ bd, int n) {
    int lane = threadIdx.x & 31;
    int node = (blockIdx.x * blockDim.x + threadIdx.x) >> 5;
    if (node >= n) return;
    float4 h = *reinterpret_cast<const float4*>(out + (size_t)node * 128 + lane * 4);
    float4 wa0 = *reinterpret_cast<const float4*>(Wa + lane * 8);
    float4 wa1 = *reinterpret_cast<const float4*>(Wa + lane * 8 + 4);
    float4 wd0 = *reinterpret_cast<const float4*>(Wd + lane * 8);
    float4 wd1 = *reinterpret_cast<const float4*>(Wd + lane * 8 + 4);
    float a0 = h.x * wa0.x + h.y * wa0.z + h.z * wa1.x + h.w * wa1.z;
    float a1 = h.x * wa0.y + h.y * wa0.w + h.z * wa1.y + h.w * wa1.w;
    float b0 = h.x * wd0.x + h.y * wd0.z + h.z * wd1.x + h.w * wd1.z;
    float b1 = h.x * wd0.y + h.y * wd0.w + h.z * wd1.y + h.w * wd1.w;
#pragma unroll
    for (int o = 16; o; o >>= 1) {
        a0 += __shfl_xor_sync(0xffffffffu, a0, o);
        a1 += __shfl_xor_sync(0xffffffffu, a1, o);
        b0 += __shfl_xor_sync(0xffffffffu, b0, o);
        b1 += __shfl_xor_sync(0xffffffffu, b1, o);
    }
    if (lane == 0) {
        d_ang[node * 2 + 0] = a0 + ba[0];
        d_ang[node * 2 + 1] = a1 + ba[1];
        d_dis[node * 2 + 0] = b0 + bd[0];
        d_dis[node * 2 + 1] = b1 + bd[1];
    }
}

// ---------------- per-edge predictions ----------------
__global__ void pred_kernel(const int* __restrict__ edges, float* __restrict__ pout, int E) {
    int e = blockIdx.x * blockDim.x + threadIdx.x;
    if (e < E) {
        int s = edges[2 * e];
        int d = edges[2 * e + 1];
        float2 as2 = *reinterpret_cast<const float2*>(d_ang + 2 * (size_t)s);
        float2 ad2 = *reinterpret_cast<const float2*>(d_ang + 2 * (size_t)d);
        float2 ds2 = *reinterpret_cast<const float2*>(d_dis + 2 * (size_t)s);
        float2 dd2 = *reinterpret_cast<const float2*>(d_dis + 2 * (size_t)d);
        pout[2 * (size_t)e + 0] = as2.x * ad2.x + as2.y * ad2.y;
        pout[2 * (size_t)e + 1] = ds2.x * dd2.x + ds2.y * dd2.y;
    }
}

// ---------------- launch ----------------
extern "C" void kernel_launch(void* const* d_in, const int* in_sizes, int n_in,
                              void* d_out, int out_size) {
    const float* image = (const float*)d_in[0];
    const float* text  = (const float*)d_in[1];
    const int*   ci    = (const int*)d_in[2];
    // d_in[3] gt_indices: unused
    const int*   edges = (const int*)d_in[4];
    const float* ars   = (const float*)d_in[5];
    const float* Wi    = (const float*)d_in[6];
    const float* bi    = (const float*)d_in[7];
    const float* Wt    = (const float*)d_in[8];
    const float* bt    = (const float*)d_in[9];
    const float* W0    = (const float*)d_in[10];
    const float* as0   = (const float*)d_in[11];
    const float* ad0   = (const float*)d_in[12];
    const float* b0    = (const float*)d_in[13];
    const float* W1    = (const float*)d_in[14];
    const float* as1   = (const float*)d_in[15];
    const float* ad1   = (const float*)d_in[16];
    const float* b1    = (const float*)d_in[17];
    const float* Wa    = (const float*)d_in[18];
    const float* ba    = (const float*)d_in[19];
    const float* Wd    = (const float*)d_in[20];
    const float* bd    = (const float*)d_in[21];

    int N = in_sizes[0] / 512;
    int E = in_sizes[4] / 2;

    float* out  = (float*)d_out;
    float* pred = out + (size_t)N * 128;

    // device-symbol addresses (plain runtime queries, capture-safe)
    float *node_p = nullptr, *g_p = nullptr, *h_p = nullptr, *w0p_p = nullptr;
    cudaGetSymbolAddress((void**)&node_p, d_node);
    cudaGetSymbolAddress((void**)&g_p,    d_g);
    cudaGetSymbolAddress((void**)&h_p,    d_h);
    cudaGetSymbolAddress((void**)&w0p_p,  d_w0p);

    const int T = 256;
    dim3 gemm_grid1((N + 127) / 128, 1);
    dim3 gemm_grid2((N + 127) / 128, 2);
    int warp_grid = (N + 7) / 8;            // 8 warps per 256-thread block
    int edge_grid = (E + T - 1) / T;

    // 0) zero node buffer + counts
    zero_kernel<<<2048, T>>>((int)((size_t)N * FEATP / 4), N);
    // 1) pad W0
    w0pad_kernel<<<(FEATP * HID + T - 1) / T, T>>>(W0);
    // 2) input projections -> gelu -> scatter into d_node
    gemm_kernel<<<gemm_grid1, T>>>(image, 512, 512, Wi, 64, bi, node_p,      FEATP, ci, 1, N);
    gemm_kernel<<<gemm_grid1, T>>>(text,  768, 768, Wt, 64, bt, node_p + 64, FEATP, ci, 1, N);
    ars_kernel<<<(N + T - 1) / T, T>>>(ars, ci, N);
    // 3) CSR build
    count_kernel<<<edge_grid, T>>>(edges, E);
    scan_kernel<<<1, 1024>>>(N);
    scatter_kernel<<<edge_grid, T>>>(edges, E);
    // 4) GAT layer 0
    gemm_kernel<<<gemm_grid2, T>>>(node_p, FEATP, FEATP, w0p_p, HID, nullptr, g_p, HID, nullptr, 0, N);
    attn_kernel<<<warp_grid, T>>>(g_p, as0, ad0, N);
    agg_kernel<<<warp_grid, T>>>(g_p, b0, h_p, /*relu*/1, N);
    // 5) GAT layer 1 -> gelu -> final out
    gemm_kernel<<<gemm_grid2, T>>>(h_p, HID, HID, W1, HID, nullptr, g_p, HID, nullptr, 0, N);
    attn_kernel<<<warp_grid, T>>>(g_p, as1, ad1, N);
    agg_kernel<<<warp_grid, T>>>(g_p, b1, out, /*gelu*/2, N);
    // 6) heads + per-edge predictions
    head_kernel<<<warp_grid, T>>>(out, Wa, ba, Wd, bd, N);
    pred_kernel<<<edge_grid, T>>>(edges, pred, E);
}

// round 15
// speedup vs baseline: 1.0000x; 1.0000x over previous
#include <cuda_runtime.h>
#include <math.h>

// Problem constants (match reference)
#define NNODES 100000
#define NEDGES 1600000
#define FEATP  144          // FEAT=131 padded to multiple of 16
#define HID    128

// ---------------- scratch (device globals; no allocation) ----------------
__device__ float d_node[(size_t)NNODES * FEATP];   // gelu'd concat features
__device__ float d_g  [(size_t)NNODES * HID];      // per-layer GEMM output h = x@W
__device__ float d_h  [(size_t)NNODES * HID];      // layer0 aggregated (relu) output
__device__ float d_w0p[FEATP * HID];               // padded W0
__device__ float d_as [NNODES];
__device__ float d_ad [NNODES];
__device__ float d_ang[NNODES * 2];
__device__ float d_dis[NNODES * 2];
__device__ int   d_counts[NNODES];
__device__ int   d_rowptr[NNODES + 1];
__device__ int   d_woff  [NNODES];
__device__ int   d_csrsrc[NEDGES];

// ---------------- helpers ----------------
__device__ __forceinline__ unsigned long long pk2(float lo, float hi) {
    unsigned long long r;
    asm("mov.b64 %0, {%1,%2};" : "=l"(r) : "f"(lo), "f"(hi));
    return r;
}
__device__ __forceinline__ float2 upk2(unsigned long long v) {
    float2 f;
    asm("mov.b64 {%0,%1}, %2;" : "=f"(f.x), "=f"(f.y) : "l"(v));
    return f;
}
__device__ __forceinline__ void ffma2(unsigned long long& d, unsigned long long a, unsigned long long b) {
    asm("fma.rn.f32x2 %0, %1, %2, %0;" : "+l"(d) : "l"(a), "l"(b));
}
__device__ __forceinline__ float gelu_exact(float x) {
    return 0.5f * x * (1.0f + erff(x * 0.70710678118654752440f));
}
__device__ __forceinline__ float lrelu(float x) { return x >= 0.f ? x : 0.2f * x; }

// ---------------- zero scratch ----------------
__global__ void zero_kernel(int nf4, int n) {
    int stride = gridDim.x * blockDim.x;
    int i = blockIdx.x * blockDim.x + threadIdx.x;
    float4 z = make_float4(0.f, 0.f, 0.f, 0.f);
    for (int j = i; j < nf4; j += stride) reinterpret_cast<float4*>(d_node)[j] = z;
    for (int j = i; j < n;   j += stride) d_counts[j] = 0;
}

// ---------------- pad W0 (131x128 -> 144x128, zero rows) ----------------
__global__ void w0pad_kernel(const float* __restrict__ W0) {
    int i = blockIdx.x * blockDim.x + threadIdx.x;
    if (i < FEATP * HID) {
        int r = i / HID;
        d_w0p[i] = (r < 131) ? W0[i] : 0.f;
    }
}

// ---------------- generic fp32 GEMM with f32x2 ----------------
// C[scatter(m), cb+n] = act( sum_k A[m,k]*W[k, cb+n] + bias[cb+n] )
// tile: BM=128, BN=64 (per blockIdx.y), BK=16; 256 threads; thread = 4 rows x 8 cols
__global__ __launch_bounds__(256)
void gemm_kernel(const float* __restrict__ A, int lda, int K,
                 const float* __restrict__ W, int ldw,
                 const float* __restrict__ bias,
                 float* __restrict__ C, int ldc,
                 const int* __restrict__ scatter,
                 int act, int nrows)
{
    __shared__ float As[16][129];
    __shared__ float Bs[16][64];

    int tid   = threadIdx.x;
    int mbase = blockIdx.x * 128;
    int cb    = blockIdx.y * 64;

    int tm = (tid / 8) * 4;       // 0..124
    int tn = (tid % 8) * 8;       // 0..56

    unsigned long long acc[4][4];
#pragma unroll
    for (int i = 0; i < 4; i++)
#pragma unroll
        for (int j = 0; j < 4; j++) acc[i][j] = 0ull;

    int arow = tid / 4;           // 0..63
    int acol = (tid % 4) * 4;     // 0..12
    int wrow = tid / 16;          // 0..15
    int wcol = (tid % 16) * 4;    // 0..60

    for (int k0 = 0; k0 < K; k0 += 16) {
#pragma unroll
        for (int p = 0; p < 2; p++) {
            int r = mbase + arow + p * 64;
            float4 v = make_float4(0.f, 0.f, 0.f, 0.f);
            if (r < nrows) v = *reinterpret_cast<const float4*>(A + (size_t)r * lda + k0 + acol);
            As[acol + 0][arow + p * 64] = v.x;
            As[acol + 1][arow + p * 64] = v.y;
            As[acol + 2][arow + p * 64] = v.z;
            As[acol + 3][arow + p * 64] = v.w;
        }
        {
            float4 v = *reinterpret_cast<const float4*>(W + (size_t)(k0 + wrow) * ldw + cb + wcol);
            *reinterpret_cast<float4*>(&Bs[wrow][wcol]) = v;
        }
        __syncthreads();

#pragma unroll
        for (int k = 0; k < 16; k++) {
            unsigned long long a2[4];
#pragma unroll
            for (int i = 0; i < 4; i++) { float a = As[k][tm + i]; a2[i] = pk2(a, a); }
            float4 bA = *reinterpret_cast<const float4*>(&Bs[k][tn]);
            float4 bB = *reinterpret_cast<const float4*>(&Bs[k][tn + 4]);
            unsigned long long b2[4];
            b2[0] = pk2(bA.x, bA.y); b2[1] = pk2(bA.z, bA.w);
            b2[2] = pk2(bB.x, bB.y); b2[3] = pk2(bB.z, bB.w);
#pragma unroll
            for (int i = 0; i < 4; i++)
#pragma unroll
                for (int j = 0; j < 4; j++) ffma2(acc[i][j], a2[i], b2[j]);
        }
        __syncthreads();
    }

#pragma unroll
    for (int i = 0; i < 4; i++) {
        int r = mbase + tm + i;
        if (r >= nrows) break;
        int tr = scatter ? scatter[r] : r;
        float o[8];
#pragma unroll
        for (int j = 0; j < 4; j++) { float2 f = upk2(acc[i][j]); o[2 * j] = f.x; o[2 * j + 1] = f.y; }
#pragma unroll
        for (int j = 0; j < 8; j++) {
            float v = o[j] + (bias ? bias[cb + tn + j] : 0.f);
            if (act == 1) v = gelu_exact(v);
            o[j] = v;
        }
        float* dst = C + (size_t)tr * ldc + cb + tn;
        *reinterpret_cast<float4*>(dst)     = make_float4(o[0], o[1], o[2], o[3]);
        *reinterpret_cast<float4*>(dst + 4) = make_float4(o[4], o[5], o[6], o[7]);
    }
}

// ---------------- ars columns (128..130) with gelu, scattered ----------------
__global__ void ars_kernel(const float* __restrict__ ars, const int* __restrict__ ci, int n) {
    int r = blockIdx.x * blockDim.x + threadIdx.x;
    if (r < n) {
        int t = ci[r];
        float* dst = d_node + (size_t)t * FEATP + 128;
        dst[0] = gelu_exact(ars[r * 3 + 0]);
        dst[1] = gelu_exact(ars[r * 3 + 1]);
        dst[2] = gelu_exact(ars[r * 3 + 2]);
    }
}

// ---------------- CSR build ----------------
__global__ void count_kernel(const int* __restrict__ edges, int E) {
    int e = blockIdx.x * blockDim.x + threadIdx.x;
    if (e < E) atomicAdd(&d_counts[edges[2 * e + 1]], 1);
}

__global__ void scan_kernel(int n) {
    __shared__ int sm[1024];
    int tid = threadIdx.x;
    int per = (n + 1023) >> 10;
    int start = tid * per;
    int s = 0;
    for (int i = 0; i < per; i++) { int idx = start + i; if (idx < n) s += d_counts[idx]; }
    sm[tid] = s;
    __syncthreads();
    for (int off = 1; off < 1024; off <<= 1) {
        int v = (tid >= off) ? sm[tid - off] : 0;
        __syncthreads();
        sm[tid] += v;
        __syncthreads();
    }
    int run = sm[tid] - s;   // exclusive prefix
    for (int i = 0; i < per; i++) {
        int idx = start + i;
        if (idx < n) { d_rowptr[idx] = run; d_woff[idx] = run; run += d_counts[idx]; }
    }
    if (tid == 1023) d_rowptr[n] = sm[1023];
}

__global__ void scatter_kernel(const int* __restrict__ edges, int E) {
    int e = blockIdx.x * blockDim.x + threadIdx.x;
    if (e < E) {
        int s = edges[2 * e];
        int d = edges[2 * e + 1];
        int p = atomicAdd(&d_woff[d], 1);
        d_csrsrc[p] = s;
    }
}

// ---------------- attention scores a_s, a_d (warp per node) ----------------
__global__ void attn_kernel(const float* __restrict__ g,
                            const float* __restrict__ av_s,
                            const float* __restrict__ av_d, int n) {
    int lane = threadIdx.x & 31;
    int node = (blockIdx.x * blockDim.x + threadIdx.x) >> 5;
    if (node >= n) return;
    float4 h = *reinterpret_cast<const float4*>(g + (size_t)node * 128 + lane * 4);
    float4 a = *reinterpret_cast<const float4*>(av_s + lane * 4);
    float4 b = *reinterpret_cast<const float4*>(av_d + lane * 4);
    float ps = h.x * a.x + h.y * a.y + h.z * a.z + h.w * a.w;
    float pd = h.x * b.x + h.y * b.y + h.z * b.z + h.w * b.w;
#pragma unroll
    for (int o = 16; o; o >>= 1) {
        ps += __shfl_xor_sync(0xffffffffu, ps, o);
        pd += __shfl_xor_sync(0xffffffffu, pd, o);
    }
    if (lane == 0) { d_as[node] = ps; d_ad[node] = pd; }
}

// ---------------- GAT aggregation (warp per destination node) ----------------
// act: 1=relu, 2=gelu
__global__ void agg_kernel(const float* __restrict__ g,
                           const float* __restrict__ bias,
                           float* __restrict__ out, int act, int n) {
    int lane = threadIdx.x & 31;
    int node = (blockIdx.x * blockDim.x + threadIdx.x) >> 5;
    if (node >= n) return;

    float adv = d_ad[node];
    float e_self = lrelu(d_as[node] + adv);
    int r0 = d_rowptr[node], r1 = d_rowptr[node + 1];

    // pass 1: segment max (includes self loop)
    float m = e_self;
    for (int j = r0 + lane; j < r1; j += 32)
        m = fmaxf(m, lrelu(d_as[d_csrsrc[j]] + adv));
#pragma unroll
    for (int o = 16; o; o >>= 1) m = fmaxf(m, __shfl_xor_sync(0xffffffffu, m, o));

    // pass 2: weighted accumulate (all lanes walk all edges; lane owns 4 cols)
    float wself = __expf(e_self - m);
    float denom = wself;
    float4 hv = *reinterpret_cast<const float4*>(g + (size_t)node * 128 + lane * 4);
    float4 acc;
    acc.x = wself * hv.x; acc.y = wself * hv.y; acc.z = wself * hv.z; acc.w = wself * hv.w;
    for (int j = r0; j < r1; ++j) {
        int s = d_csrsrc[j];
        float w = __expf(lrelu(d_as[s] + adv) - m);
        denom += w;
        float4 hs = *reinterpret_cast<const float4*>(g + (size_t)s * 128 + lane * 4);
        acc.x += w * hs.x; acc.y += w * hs.y; acc.z += w * hs.z; acc.w += w * hs.w;
    }
    float inv = 1.f / (denom + 1e-16f);
    float4 bv = *reinterpret_cast<const float4*>(bias + lane * 4);
    float4 o;
    o.x = acc.x * inv + bv.x; o.y = acc.y * inv + bv.y;
    o.z = acc.z * inv + bv.z; o.w = acc.w * inv + bv.w;
    if (act == 1) {
        o.x = fmaxf(o.x, 0.f); o.y = fmaxf(o.y, 0.f); o.z = fmaxf(o.z, 0.f); o.w = fmaxf(o.w, 0.f);
    } else {
        o.x = gelu_exact(o.x); o.y = gelu_exact(o.y); o.z = gelu_exact(o.z); o.w = gelu_exact(o.w);
    }
    *reinterpret_cast<float4*>(out + (size_t)node * 128 + lane * 4) = o;
}

// ---------------- heads: angles/dists (warp per node) ----------------
__global__ void head_kernel(const float* __restrict__ out,
                            const float* __restrict__ Wa, const float* __restrict__ ba,
                            const float* __restrict__ Wd, const float* __restrict__ bd, int n) {
    int lane = threadIdx.x & 31;
    int node = (blockIdx.x * blockDim.x + threadIdx.x) >> 5;
    if (node >= n) return;
    float4 h = *reinterpret_cast<const float4*>(out + (size_t)node * 128 + lane * 4);
    float4 wa0 = *reinterpret_cast<const float4*>(Wa + lane * 8);
    float4 wa1 = *reinterpret_cast<const float4*>(Wa + lane * 8 + 4);
    float4 wd0 = *reinterpret_cast<const float4*>(Wd + lane * 8);
    float4 wd1 = *reinterpret_cast<const float4*>(Wd + lane * 8 + 4);
    float a0 = h.x * wa0.x + h.y * wa0.z + h.z * wa1.x + h.w * wa1.z;
    float a1 = h.x * wa0.y + h.y * wa0.w + h.z * wa1.y + h.w * wa1.w;
    float b0 = h.x * wd0.x + h.y * wd0.z + h.z * wd1.x + h.w * wd1.z;
    float b1 = h.x * wd0.y + h.y * wd0.w + h.z * wd1.y + h.w * wd1.w;
#pragma unroll
    for (int o = 16; o; o >>= 1) {
        a0 += __shfl_xor_sync(0xffffffffu, a0, o);
        a1 += __shfl_xor_sync(0xffffffffu, a1, o);
        b0 += __shfl_xor_sync(0xffffffffu, b0, o);
        b1 += __shfl_xor_sync(0xffffffffu, b1, o);
    }
    if (lane == 0) {
        d_ang[node * 2 + 0] = a0 + ba[0];
        d_ang[node * 2 + 1] = a1 + ba[1];
        d_dis[node * 2 + 0] = b0 + bd[0];
        d_dis[node * 2 + 1] = b1 + bd[1];
    }
}

// ---------------- per-edge predictions ----------------
__global__ void pred_kernel(const int* __restrict__ edges, float* __restrict__ pout, int E) {
    int e = blockIdx.x * blockDim.x + threadIdx.x;
    if (e < E) {
        int s = edges[2 * e];
        int d = edges[2 * e + 1];
        float2 as2 = *reinterpret_cast<const float2*>(d_ang + 2 * (size_t)s);
        float2 ad2 = *reinterpret_cast<const float2*>(d_ang + 2 * (size_t)d);
        float2 ds2 = *reinterpret_cast<const float2*>(d_dis + 2 * (size_t)s);
        float2 dd2 = *reinterpret_cast<const float2*>(d_dis + 2 * (size_t)d);
        pout[2 * (size_t)e + 0] = as2.x * ad2.x + as2.y * ad2.y;
        pout[2 * (size_t)e + 1] = ds2.x * dd2.x + ds2.y * dd2.y;
    }
}

// ---------------- launch ----------------
extern "C" void kernel_launch(void* const* d_in, const int* in_sizes, int n_in,
                              void* d_out, int out_size) {
    const float* image = (const float*)d_in[0];
    const float* text  = (const float*)d_in[1];
    const int*   ci    = (const int*)d_in[2];
    // d_in[3] gt_indices: unused
    const int*   edges = (const int*)d_in[4];
    const float* ars   = (const float*)d_in[5];
    const float* Wi    = (const float*)d_in[6];
    const float* bi    = (const float*)d_in[7];
    const float* Wt    = (const float*)d_in[8];
    const float* bt    = (const float*)d_in[9];
    const float* W0    = (const float*)d_in[10];
    const float* as0   = (const float*)d_in[11];
    const float* ad0   = (const float*)d_in[12];
    const float* b0    = (const float*)d_in[13];
    const float* W1    = (const float*)d_in[14];
    const float* as1   = (const float*)d_in[15];
    const float* ad1   = (const float*)d_in[16];
    const float* b1    = (const float*)d_in[17];
    const float* Wa    = (const float*)d_in[18];
    const float* ba    = (const float*)d_in[19];
    const float* Wd    = (const float*)d_in[20];
    const float* bd    = (const float*)d_in[21];

    int N = in_sizes[0] / 512;
    int E = in_sizes[4] / 2;

    float* out  = (float*)d_out;
    float* pred = out + (size_t)N * 128;

    // device-symbol addresses (plain runtime queries, capture-safe)
    float *node_p = nullptr, *g_p = nullptr, *h_p = nullptr, *w0p_p = nullptr;
    cudaGetSymbolAddress((void**)&node_p, d_node);
    cudaGetSymbolAddress((void**)&g_p,    d_g);
    cudaGetSymbolAddress((void**)&h_p,    d_h);
    cudaGetSymbolAddress((void**)&w0p_p,  d_w0p);

    const int T = 256;
    dim3 gemm_grid1((N + 127) / 128, 1);
    dim3 gemm_grid2((N + 127) / 128, 2);
    int warp_grid = (N + 7) / 8;            // 8 warps per 256-thread block
    int edge_grid = (E + T - 1) / T;

    // 0) zero node buffer + counts
    zero_kernel<<<2048, T>>>((int)((size_t)N * FEATP / 4), N);
    // 1) pad W0
    w0pad_kernel<<<(FEATP * HID + T - 1) / T, T>>>(W0);
    // 2) input projections -> gelu -> scatter into d_node
    gemm_kernel<<<gemm_grid1, T>>>(image, 512, 512, Wi, 64, bi, node_p,      FEATP, ci, 1, N);
    gemm_kernel<<<gemm_grid1, T>>>(text,  768, 768, Wt, 64, bt, node_p + 64, FEATP, ci, 1, N);
    ars_kernel<<<(N + T - 1) / T, T>>>(ars, ci, N);
    // 3) CSR build
    count_kernel<<<edge_grid, T>>>(edges, E);
    scan_kernel<<<1, 1024>>>(N);
    scatter_kernel<<<edge_grid, T>>>(edges, E);
    // 4) GAT layer 0
    gemm_kernel<<<gemm_grid2, T>>>(node_p, FEATP, FEATP, w0p_p, HID, nullptr, g_p, HID, nullptr, 0, N);
    attn_kernel<<<warp_grid, T>>>(g_p, as0, ad0, N);
    agg_kernel<<<warp_grid, T>>>(g_p, b0, h_p, /*relu*/1, N);
    // 5) GAT layer 1 -> gelu -> final out
    gemm_kernel<<<gemm_grid2, T>>>(h_p, HID, HID, W1, HID, nullptr, g_p, HID, nullptr, 0, N);
    attn_kernel<<<warp_grid, T>>>(g_p, as1, ad1, N);
    agg_kernel<<<warp_grid, T>>>(g_p, b1, out, /*gelu*/2, N);
    // 6) heads + per-edge predictions
    head_kernel<<<warp_grid, T>>>(out, Wa, ba, Wd, bd, N);
    pred_kernel<<<edge_grid, T>>>(edges, pred, E);
}

// round 16
// speedup vs baseline: 1.0014x; 1.0013x over previous
#include <cuda_runtime.h>
#include <math.h>

// Problem constants (match reference)
#define NNODES 100000
#define NEDGES 1600000
#define FEATP  144          // FEAT=131 padded to multiple of 16
#define HID    128

// ---------------- scratch (device globals; no allocation) ----------------
__device__ float d_node[(size_t)NNODES * FEATP];   // gelu'd concat features
__device__ float d_g  [(size_t)NNODES * HID];      // per-layer GEMM output h = x@W
__device__ float d_h  [(size_t)NNODES * HID];      // layer0 aggregated (relu) output
__device__ float d_w0p[FEATP * HID];               // padded W0
__device__ float d_as [NNODES];
__device__ float d_ad [NNODES];
__device__ float d_ang[NNODES * 2];
__device__ float d_dis[NNODES * 2];
__device__ int   d_counts[NNODES];
__device__ int   d_rowptr[NNODES + 1];
__device__ int   d_woff  [NNODES];
__device__ int   d_csrsrc[NEDGES];

// ---------------- helpers ----------------
__device__ __forceinline__ unsigned long long pk2(float lo, float hi) {
    unsigned long long r;
    asm("mov.b64 %0, {%1,%2};" : "=l"(r) : "f"(lo), "f"(hi));
    return r;
}
__device__ __forceinline__ float2 upk2(unsigned long long v) {
    float2 f;
    asm("mov.b64 {%0,%1}, %2;" : "=f"(f.x), "=f"(f.y) : "l"(v));
    return f;
}
__device__ __forceinline__ void ffma2(unsigned long long& d, unsigned long long a, unsigned long long b) {
    asm("fma.rn.f32x2 %0, %1, %2, %0;" : "+l"(d) : "l"(a), "l"(b));
}
__device__ __forceinline__ float gelu_exact(float x) {
    return 0.5f * x * (1.0f + erff(x * 0.70710678118654752440f));
}
__device__ __forceinline__ float lrelu(float x) { return x >= 0.f ? x : 0.2f * x; }

// ---------------- zero scratch ----------------
__global__ void zero_kernel(int nf4, int n) {
    int stride = gridDim.x * blockDim.x;
    int i = blockIdx.x * blockDim.x + threadIdx.x;
    float4 z = make_float4(0.f, 0.f, 0.f, 0.f);
    for (int j = i; j < nf4; j += stride) reinterpret_cast<float4*>(d_node)[j] = z;
    for (int j = i; j < n;   j += stride) d_counts[j] = 0;
}

// ---------------- pad W0 (131x128 -> 144x128, zero rows) ----------------
__global__ void w0pad_kernel(const float* __restrict__ W0) {
    int i = blockIdx.x * blockDim.x + threadIdx.x;
    if (i < FEATP * HID) {
        int r = i / HID;
        d_w0p[i] = (r < 131) ? W0[i] : 0.f;
    }
}

// ---------------- generic fp32 GEMM with f32x2 ----------------
// C[scatter(m), cb+n] = act( sum_k A[m,k]*W[k, cb+n] + bias[cb+n] )
// tile: BM=128, BN=64 (per blockIdx.y), BK=16; 256 threads; thread = 4 rows x 8 cols
__global__ __launch_bounds__(256)
void gemm_kernel(const float* __restrict__ A, int lda, int K,
                 const float* __restrict__ W, int ldw,
                 const float* __restrict__ bias,
                 float* __restrict__ C, int ldc,
                 const int* __restrict__ scatter,
                 int act, int nrows)
{
    __shared__ float As[16][129];
    __shared__ float Bs[16][64];

    int tid   = threadIdx.x;
    int mbase = blockIdx.x * 128;
    int cb    = blockIdx.y * 64;

    int tm = (tid / 8) * 4;       // 0..124
    int tn = (tid % 8) * 8;       // 0..56

    unsigned long long acc[4][4];
#pragma unroll
    for (int i = 0; i < 4; i++)
#pragma unroll
        for (int j = 0; j < 4; j++) acc[i][j] = 0ull;

    int arow = tid / 4;           // 0..63
    int acol = (tid % 4) * 4;     // 0..12
    int wrow = tid / 16;          // 0..15
    int wcol = (tid % 16) * 4;    // 0..60

    for (int k0 = 0; k0 < K; k0 += 16) {
#pragma unroll
        for (int p = 0; p < 2; p++) {
            int r = mbase + arow + p * 64;
            float4 v = make_float4(0.f, 0.f, 0.f, 0.f);
            if (r < nrows) v = *reinterpret_cast<const float4*>(A + (size_t)r * lda + k0 + acol);
            As[acol + 0][arow + p * 64] = v.x;
            As[acol + 1][arow + p * 64] = v.y;
            As[acol + 2][arow + p * 64] = v.z;
            As[acol + 3][arow + p * 64] = v.w;
        }
        {
            float4 v = *reinterpret_cast<const float4*>(W + (size_t)(k0 + wrow) * ldw + cb + wcol);
            *reinterpret_cast<float4*>(&Bs[wrow][wcol]) = v;
        }
        __syncthreads();

#pragma unroll
        for (int k = 0; k < 16; k++) {
            unsigned long long a2[4];
#pragma unroll
            for (int i = 0; i < 4; i++) { float a = As[k][tm + i]; a2[i] = pk2(a, a); }
            float4 bA = *reinterpret_cast<const float4*>(&Bs[k][tn]);
            float4 bB = *reinterpret_cast<const float4*>(&Bs[k][tn + 4]);
            unsigned long long b2[4];
            b2[0] = pk2(bA.x, bA.y); b2[1] = pk2(bA.z, bA.w);
            b2[2] = pk2(bB.x, bB.y); b2[3] = pk2(bB.z, bB.w);
#pragma unroll
            for (int i = 0; i < 4; i++)
#pragma unroll
                for (int j = 0; j < 4; j++) ffma2(acc[i][j], a2[i], b2[j]);
        }
        __syncthreads();
    }

#pragma unroll
    for (int i = 0; i < 4; i++) {
        int r = mbase + tm + i;
        if (r >= nrows) break;
        int tr = scatter ? scatter[r] : r;
        float o[8];
#pragma unroll
        for (int j = 0; j < 4; j++) { float2 f = upk2(acc[i][j]); o[2 * j] = f.x; o[2 * j + 1] = f.y; }
#pragma unroll
        for (int j = 0; j < 8; j++) {
            float v = o[j] + (bias ? bias[cb + tn + j] : 0.f);
            if (act == 1) v = gelu_exact(v);
            o[j] = v;
        }
        float* dst = C + (size_t)tr * ldc + cb + tn;
        *reinterpret_cast<float4*>(dst)     = make_float4(o[0], o[1], o[2], o[3]);
        *reinterpret_cast<float4*>(dst + 4) = make_float4(o[4], o[5], o[6], o[7]);
    }
}

// ---------------- ars columns (128..130) with gelu, scattered ----------------
__global__ void ars_kernel(const float* __restrict__ ars, const int* __restrict__ ci, int n) {
    int r = blockIdx.x * blockDim.x + threadIdx.x;
    if (r < n) {
        int t = ci[r];
        float* dst = d_node + (size_t)t * FEATP + 128;
        dst[0] = gelu_exact(ars[r * 3 + 0]);
        dst[1] = gelu_exact(ars[r * 3 + 1]);
        dst[2] = gelu_exact(ars[r * 3 + 2]);
    }
}

// ---------------- CSR build ----------------
__global__ void count_kernel(const int* __restrict__ edges, int E) {
    int e = blockIdx.x * blockDim.x + threadIdx.x;
    if (e < E) atomicAdd(&d_counts[edges[2 * e + 1]], 1);
}

__global__ void scan_kernel(int n) {
    __shared__ int sm[1024];
    int tid = threadIdx.x;
    int per = (n + 1023) >> 10;
    int start = tid * per;
    int s = 0;
    for (int i = 0; i < per; i++) { int idx = start + i; if (idx < n) s += d_counts[idx]; }
    sm[tid] = s;
    __syncthreads();
    for (int off = 1; off < 1024; off <<= 1) {
        int v = (tid >= off) ? sm[tid - off] : 0;
        __syncthreads();
        sm[tid] += v;
        __syncthreads();
    }
    int run = sm[tid] - s;   // exclusive prefix
    for (int i = 0; i < per; i++) {
        int idx = start + i;
        if (idx < n) { d_rowptr[idx] = run; d_woff[idx] = run; run += d_counts[idx]; }
    }
    if (tid == 1023) d_rowptr[n] = sm[1023];
}

__global__ void scatter_kernel(const int* __restrict__ edges, int E) {
    int e = blockIdx.x * blockDim.x + threadIdx.x;
    if (e < E) {
        int s = edges[2 * e];
        int d = edges[2 * e + 1];
        int p = atomicAdd(&d_woff[d], 1);
        d_csrsrc[p] = s;
    }
}

// ---------------- attention scores a_s, a_d (warp per node) ----------------
__global__ void attn_kernel(const float* __restrict__ g,
                            const float* __restrict__ av_s,
                            const float* __restrict__ av_d, int n) {
    int lane = threadIdx.x & 31;
    int node = (blockIdx.x * blockDim.x + threadIdx.x) >> 5;
    if (node >= n) return;
    float4 h = *reinterpret_cast<const float4*>(g + (size_t)node * 128 + lane * 4);
    float4 a = *reinterpret_cast<const float4*>(av_s + lane * 4);
    float4 b = *reinterpret_cast<const float4*>(av_d + lane * 4);
    float ps = h.x * a.x + h.y * a.y + h.z * a.z + h.w * a.w;
    float pd = h.x * b.x + h.y * b.y + h.z * b.z + h.w * b.w;
#pragma unroll
    for (int o = 16; o; o >>= 1) {
        ps += __shfl_xor_sync(0xffffffffu, ps, o);
        pd += __shfl_xor_sync(0xffffffffu, pd, o);
    }
    if (lane == 0) { d_as[node] = ps; d_ad[node] = pd; }
}

// ---------------- GAT aggregation (warp per destination node) ----------------
// act: 1=relu, 2=gelu
__global__ void agg_kernel(const float* __restrict__ g,
                           const float* __restrict__ bias,
                           float* __restrict__ out, int act, int n) {
    int lane = threadIdx.x & 31;
    int node = (blockIdx.x * blockDim.x + threadIdx.x) >> 5;
    if (node >= n) return;

    float adv = d_ad[node];
    float e_self = lrelu(d_as[node] + adv);
    int r0 = d_rowptr[node], r1 = d_rowptr[node + 1];

    // pass 1: segment max (includes self loop)
    float m = e_self;
    for (int j = r0 + lane; j < r1; j += 32)
        m = fmaxf(m, lrelu(d_as[d_csrsrc[j]] + adv));
#pragma unroll
    for (int o = 16; o; o >>= 1) m = fmaxf(m, __shfl_xor_sync(0xffffffffu, m, o));

    // pass 2: weighted accumulate (all lanes walk all edges; lane owns 4 cols)
    float wself = __expf(e_self - m);
    float denom = wself;
    float4 hv = *reinterpret_cast<const float4*>(g + (size_t)node * 128 + lane * 4);
    float4 acc;
    acc.x = wself * hv.x; acc.y = wself * hv.y; acc.z = wself * hv.z; acc.w = wself * hv.w;
    for (int j = r0; j < r1; ++j) {
        int s = d_csrsrc[j];
        float w = __expf(lrelu(d_as[s] + adv) - m);
        denom += w;
        float4 hs = *reinterpret_cast<const float4*>(g + (size_t)s * 128 + lane * 4);
        acc.x += w * hs.x; acc.y += w * hs.y; acc.z += w * hs.z; acc.w += w * hs.w;
    }
    float inv = 1.f / (denom + 1e-16f);
    float4 bv = *reinterpret_cast<const float4*>(bias + lane * 4);
    float4 o;
    o.x = acc.x * inv + bv.x; o.y = acc.y * inv + bv.y;
    o.z = acc.z * inv + bv.z; o.w = acc.w * inv + bv.w;
    if (act == 1) {
        o.x = fmaxf(o.x, 0.f); o.y = fmaxf(o.y, 0.f); o.z = fmaxf(o.z, 0.f); o.w = fmaxf(o.w, 0.f);
    } else {
        o.x = gelu_exact(o.x); o.y = gelu_exact(o.y); o.z = gelu_exact(o.z); o.w = gelu_exact(o.w);
    }
    *reinterpret_cast<float4*>(out + (size_t)node * 128 + lane * 4) = o;
}

// ---------------- heads: angles/dists (warp per node) ----------------
__global__ void head_kernel(const float* __restrict__ out,
                            const float* __restrict__ Wa, const float* __restrict__ ba,
                            const float* __restrict__ Wd, const float* __restrict__ bd, int n) {
    int lane = threadIdx.x & 31;
    int node = (blockIdx.x * blockDim.x + threadIdx.x) >> 5;
    if (node >= n) return;
    float4 h = *reinterpret_cast<const float4*>(out + (size_t)node * 128 + lane * 4);
    float4 wa0 = *reinterpret_cast<const float4*>(Wa + lane * 8);
    float4 wa1 = *reinterpret_cast<const float4*>(Wa + lane * 8 + 4);
    float4 wd0 = *reinterpret_cast<const float4*>(Wd + lane * 8);
    float4 wd1 = *reinterpret_cast<const float4*>(Wd + lane * 8 + 4);
    float a0 = h.x * wa0.x + h.y * wa0.z + h.z * wa1.x + h.w * wa1.z;
    float a1 = h.x * wa0.y + h.y * wa0.w + h.z * wa1.y + h.w * wa1.w;
    float b0 = h.x * wd0.x + h.y * wd0.z + h.z * wd1.x + h.w * wd1.z;
    float b1 = h.x * wd0.y + h.y * wd0.w + h.z * wd1.y + h.w * wd1.w;
#pragma unroll
    for (int o = 16; o; o >>= 1) {
        a0 += __shfl_xor_sync(0xffffffffu, a0, o);
        a1 += __shfl_xor_sync(0xffffffffu, a1, o);
        b0 += __shfl_xor_sync(0xffffffffu, b0, o);
        b1 += __shfl_xor_sync(0xffffffffu, b1, o);
    }
    if (lane == 0) {
        d_ang[node * 2 + 0] = a0 + ba[0];
        d_ang[node * 2 + 1] = a1 + ba[1];
        d_dis[node * 2 + 0] = b0 + bd[0];
        d_dis[node * 2 + 1] = b1 + bd[1];
    }
}

// ---------------- per-edge predictions ----------------
__global__ void pred_kernel(const int* __restrict__ edges, float* __restrict__ pout, int E) {
    int e = blockIdx.x * blockDim.x + threadIdx.x;
    if (e < E) {
        int s = edges[2 * e];
        int d = edges[2 * e + 1];
        float2 as2 = *reinterpret_cast<const float2*>(d_ang + 2 * (size_t)s);
        float2 ad2 = *reinterpret_cast<const float2*>(d_ang + 2 * (size_t)d);
        float2 ds2 = *reinterpret_cast<const float2*>(d_dis + 2 * (size_t)s);
        float2 dd2 = *reinterpret_cast<const float2*>(d_dis + 2 * (size_t)d);
        pout[2 * (size_t)e + 0] = as2.x * ad2.x + as2.y * ad2.y;
        pout[2 * (size_t)e + 1] = ds2.x * dd2.x + ds2.y * dd2.y;
    }
}

// ---------------- launch ----------------
extern "C" void kernel_launch(void* const* d_in, const int* in_sizes, int n_in,
                              void* d_out, int out_size) {
    const float* image = (const float*)d_in[0];
    const float* text  = (const float*)d_in[1];
    const int*   ci    = (const int*)d_in[2];
    // d_in[3] gt_indices: unused
    const int*   edges = (const int*)d_in[4];
    const float* ars   = (const float*)d_in[5];
    const float* Wi    = (const float*)d_in[6];
    const float* bi    = (const float*)d_in[7];
    const float* Wt    = (const float*)d_in[8];
    const float* bt    = (const float*)d_in[9];
    const float* W0    = (const float*)d_in[10];
    const float* as0   = (const float*)d_in[11];
    const float* ad0   = (const float*)d_in[12];
    const float* b0    = (const float*)d_in[13];
    const float* W1    = (const float*)d_in[14];
    const float* as1   = (const float*)d_in[15];
    const float* ad1   = (const float*)d_in[16];
    const float* b1    = (const float*)d_in[17];
    const float* Wa    = (const float*)d_in[18];
    const float* ba    = (const float*)d_in[19];
    const float* Wd    = (const float*)d_in[20];
    const float* bd    = (const float*)d_in[21];

    int N = in_sizes[0] / 512;
    int E = in_sizes[4] / 2;

    float* out  = (float*)d_out;
    float* pred = out + (size_t)N * 128;

    // device-symbol addresses (plain runtime queries, capture-safe)
    float *node_p = nullptr, *g_p = nullptr, *h_p = nullptr, *w0p_p = nullptr;
    cudaGetSymbolAddress((void**)&node_p, d_node);
    cudaGetSymbolAddress((void**)&g_p,    d_g);
    cudaGetSymbolAddress((void**)&h_p,    d_h);
    cudaGetSymbolAddress((void**)&w0p_p,  d_w0p);

    const int T = 256;
    dim3 gemm_grid1((N + 127) / 128, 1);
    dim3 gemm_grid2((N + 127) / 128, 2);
    int warp_grid = (N + 7) / 8;            // 8 warps per 256-thread block
    int edge_grid = (E + T - 1) / T;

    // 0) zero node buffer + counts
    zero_kernel<<<2048, T>>>((int)((size_t)N * FEATP / 4), N);
    // 1) pad W0
    w0pad_kernel<<<(FEATP * HID + T - 1) / T, T>>>(W0);
    // 2) input projections -> gelu -> scatter into d_node
    gemm_kernel<<<gemm_grid1, T>>>(image, 512, 512, Wi, 64, bi, node_p,      FEATP, ci, 1, N);
    gemm_kernel<<<gemm_grid1, T>>>(text,  768, 768, Wt, 64, bt, node_p + 64, FEATP, ci, 1, N);
    ars_kernel<<<(N + T - 1) / T, T>>>(ars, ci, N);
    // 3) CSR build
    count_kernel<<<edge_grid, T>>>(edges, E);
    scan_kernel<<<1, 1024>>>(N);
    scatter_kernel<<<edge_grid, T>>>(edges, E);
    // 4) GAT layer 0
    gemm_kernel<<<gemm_grid2, T>>>(node_p, FEATP, FEATP, w0p_p, HID, nullptr, g_p, HID, nullptr, 0, N);
    attn_kernel<<<warp_grid, T>>>(g_p, as0, ad0, N);
    agg_kernel<<<warp_grid, T>>>(g_p, b0, h_p, /*relu*/1, N);
    // 5) GAT layer 1 -> gelu -> final out
    gemm_kernel<<<gemm_grid2, T>>>(h_p, HID, HID, W1, HID, nullptr, g_p, HID, nullptr, 0, N);
    attn_kernel<<<warp_grid, T>>>(g_p, as1, ad1, N);
    agg_kernel<<<warp_grid, T>>>(g_p, b1, out, /*gelu*/2, N);
    // 6) heads + per-edge predictions
    head_kernel<<<warp_grid, T>>>(out, Wa, ba, Wd, bd, N);
    pred_kernel<<<edge_grid, T>>>(edges, pred, E);
}